// round 16
// baseline (speedup 1.0000x reference)
#include <cuda_runtime.h>
#include <cuda_bf16.h>
#include <cstdint>

#define HDIM 128
#define MH 64
#define LN_EPS 1e-5f

// ===== single fused kernel: one block per graph, float4 streaming =====
// batch is sorted, so graph b's rows are [lower_bound(b), lower_bound(b+1)).
// Each block binary-searches its range, streams it with register-resident
// per-column stats (warp = full 512B row via float4; no atomics, no scratch,
// no grid barrier), then runs the MLP for its graph.

struct MlpBufs {
    float part0[16][MH + 1];   // 4.2 KB (padded)
    float part1[4][MH + 1];    // 1 KB
    float part3[2][HDIM];      // 1 KB
    float h0[MH];
    float hb[MH];
};
union TailU {
    float4 red4[8][4][32];     // 16 KB: per-warp stats publish
    MlpBufs m;
};

__global__ void __launch_bounds__(256, 7) fused_one(
    const float* __restrict__ x, const int* __restrict__ batch, int N,
    const float* __restrict__ u,
    const float* __restrict__ W0, const float* __restrict__ b0,
    const float* __restrict__ W1, const float* __restrict__ b1,
    const float* __restrict__ W2, const float* __restrict__ b2,
    const float* __restrict__ lng, const float* __restrict__ lnb,
    const float* __restrict__ W3, const float* __restrict__ b3,
    float* __restrict__ out) {
    const int b = blockIdx.x;        // graph id
    const int t = threadIdx.x;
    const int warp = t >> 5;         // 0..7: row group (stride 8)
    const int lane = t & 31;         // covers cols [4*lane, 4*lane+4)

    __shared__ int bounds[2];
    __shared__ TailU s;
    __shared__ float concat[5 * HDIM];    // 2.5 KB

    // ---- bounds: threads 0,1 binary-search lower_bound(b), lower_bound(b+1)
    if (t < 2) {
        int target = b + t;
        int lo = 0, hi = N;
        while (lo < hi) {
            int mid = (lo + hi) >> 1;
            if (__ldg(&batch[mid]) < target) lo = mid + 1;
            else hi = mid;
        }
        bounds[t] = lo;
    }
    __syncthreads();
    const int lo = bounds[0], hi = bounds[1];
    const int cnt = hi - lo;

    // ---- stream: warp owns rows lo+warp, lo+warp+8, ...; lane owns 4 cols
    float s0 = 0.f, s1 = 0.f, s2 = 0.f, s3 = 0.f;          // sum
    float q0 = 0.f, q1 = 0.f, q2 = 0.f, q3 = 0.f;          // sumsq
    float n0 = __int_as_float(0x7F800000);                 // +inf
    float n1 = n0, n2 = n0, n3 = n0;                       // min
    float m0 = __int_as_float(0xFF800000);                 // -inf
    float m1 = m0, m2 = m0, m3 = m0;                       // max

    int r = lo + warp;
    const float4* xp = (const float4*)x + (long long)r * (HDIM / 4) + lane;
    for (; r + 8 < hi; r += 16) {    // 2 rows per warp per iter
        float4 v0 = __ldcs(xp);
        float4 v1 = __ldcs(xp + 8 * (HDIM / 4));
        s0 += v0.x; s1 += v0.y; s2 += v0.z; s3 += v0.w;
        q0 = fmaf(v0.x, v0.x, q0); q1 = fmaf(v0.y, v0.y, q1);
        q2 = fmaf(v0.z, v0.z, q2); q3 = fmaf(v0.w, v0.w, q3);
        n0 = fminf(n0, v0.x); n1 = fminf(n1, v0.y);
        n2 = fminf(n2, v0.z); n3 = fminf(n3, v0.w);
        m0 = fmaxf(m0, v0.x); m1 = fmaxf(m1, v0.y);
        m2 = fmaxf(m2, v0.z); m3 = fmaxf(m3, v0.w);
        s0 += v1.x; s1 += v1.y; s2 += v1.z; s3 += v1.w;
        q0 = fmaf(v1.x, v1.x, q0); q1 = fmaf(v1.y, v1.y, q1);
        q2 = fmaf(v1.z, v1.z, q2); q3 = fmaf(v1.w, v1.w, q3);
        n0 = fminf(n0, v1.x); n1 = fminf(n1, v1.y);
        n2 = fminf(n2, v1.z); n3 = fminf(n3, v1.w);
        m0 = fmaxf(m0, v1.x); m1 = fmaxf(m1, v1.y);
        m2 = fmaxf(m2, v1.z); m3 = fmaxf(m3, v1.w);
        xp += 16 * (HDIM / 4);
    }
    for (; r < hi; r += 8) {
        float4 v = __ldcs(xp);
        s0 += v.x; s1 += v.y; s2 += v.z; s3 += v.w;
        q0 = fmaf(v.x, v.x, q0); q1 = fmaf(v.y, v.y, q1);
        q2 = fmaf(v.z, v.z, q2); q3 = fmaf(v.w, v.w, q3);
        n0 = fminf(n0, v.x); n1 = fminf(n1, v.y);
        n2 = fminf(n2, v.z); n3 = fminf(n3, v.w);
        m0 = fmaxf(m0, v.x); m1 = fmaxf(m1, v.y);
        m2 = fmaxf(m2, v.z); m3 = fmaxf(m3, v.w);
        xp += 8 * (HDIM / 4);
    }

    // ---- each warp publishes its 4-col stats (float4, conflict-free) ----
    s.red4[warp][0][lane] = make_float4(s0, s1, s2, s3);
    s.red4[warp][1][lane] = make_float4(q0, q1, q2, q3);
    s.red4[warp][2][lane] = make_float4(n0, n1, n2, n3);
    s.red4[warp][3][lane] = make_float4(m0, m1, m2, m3);
    __syncthreads();

    // ---- combine across 8 warps; thread t<128 builds concat for col t ----
    if (t < HDIM) {
        const int wd = t >> 2, ce = t & 3;   // float4 index, component
        float ss = 0.f, qq = 0.f;
        float nn = __int_as_float(0x7F800000);
        float mm = __int_as_float(0xFF800000);
#pragma unroll
        for (int w = 0; w < 8; ++w) {
            const float* rs = (const float*)&s.red4[w][0][wd];
            const float* rq = (const float*)&s.red4[w][1][wd];
            const float* rn = (const float*)&s.red4[w][2][wd];
            const float* rm = (const float*)&s.red4[w][3][wd];
            ss += rs[ce];
            qq += rq[ce];
            nn = fminf(nn, rn[ce]);
            mm = fmaxf(mm, rm[ce]);
        }
        float cv = fmaxf((float)cnt, 1.0f);
        float me = ss / cv;
        concat[t]            = u[b * HDIM + t];
        concat[HDIM + t]     = ss;
        concat[2 * HDIM + t] = nn;
        concat[3 * HDIM + t] = mm;
        concat[4 * HDIM + t] = qq / cv - me * me;
    }
    __syncthreads();

    // ================= MLP (R7-proven structure, single graph) =============
    // layer 0: 640 -> 64; 16-way K-split, 4 outputs/thread via float4
    {
        const int mg = (t & 15) * 4;
        const int q  = t >> 4;           // 0..15
        float a0 = 0.f, a1 = 0.f, a2 = 0.f, a3 = 0.f;
        const int k0 = q * 40;
#pragma unroll 8
        for (int k = k0; k < k0 + 40; ++k) {
            float c = concat[k];
            float4 w = *(const float4*)&W0[k * MH + mg];
            a0 = fmaf(c, w.x, a0);
            a1 = fmaf(c, w.y, a1);
            a2 = fmaf(c, w.z, a2);
            a3 = fmaf(c, w.w, a3);
        }
        s.m.part0[q][mg + 0] = a0;
        s.m.part0[q][mg + 1] = a1;
        s.m.part0[q][mg + 2] = a2;
        s.m.part0[q][mg + 3] = a3;
    }
    __syncthreads();
    if (t < MH) {
        float sum = 0.f;
#pragma unroll
        for (int q = 0; q < 16; ++q) sum += s.m.part0[q][t];
        s.m.h0[t] = fmaxf(sum + b0[t], 0.f);
    }
    __syncthreads();

    // layer 1: 64 -> 64; 4-way K-split
    {
        const int m = t & 63;
        const int q = t >> 6;
        float acc = 0.f;
        const int k0 = q * 16;
#pragma unroll
        for (int k = k0; k < k0 + 16; ++k)
            acc = fmaf(s.m.h0[k], __ldg(&W1[k * MH + m]), acc);
        s.m.part1[q][m] = acc;
    }
    __syncthreads();
    if (t < MH)
        s.m.hb[t] = fmaxf(s.m.part1[0][t] + s.m.part1[1][t] + s.m.part1[2][t] +
                          s.m.part1[3][t] + b1[t], 0.f);
    __syncthreads();

    // layer 2: 64 -> 64; 4-way K-split
    {
        const int m = t & 63;
        const int q = t >> 6;
        float acc = 0.f;
        const int k0 = q * 16;
#pragma unroll
        for (int k = k0; k < k0 + 16; ++k)
            acc = fmaf(s.m.hb[k], __ldg(&W2[k * MH + m]), acc);
        s.m.part1[q][m] = acc;
    }
    __syncthreads();
    if (t < MH)
        s.m.h0[t] = fmaxf(s.m.part1[0][t] + s.m.part1[1][t] + s.m.part1[2][t] +
                          s.m.part1[3][t] + b2[t], 0.f);
    __syncthreads();

    // layernorm over 64 features (warp 0, shuffle reduce)
    if (t < 32) {
        float v0 = s.m.h0[t], v1 = s.m.h0[t + 32];
        float sum = v0 + v1;
#pragma unroll
        for (int o = 16; o > 0; o >>= 1) sum += __shfl_xor_sync(0xFFFFFFFF, sum, o);
        float mu = sum * (1.0f / MH);
        float d0 = v0 - mu, d1 = v1 - mu;
        float vs = d0 * d0 + d1 * d1;
#pragma unroll
        for (int o = 16; o > 0; o >>= 1) vs += __shfl_xor_sync(0xFFFFFFFF, vs, o);
        float rstd = rsqrtf(vs * (1.0f / MH) + LN_EPS);
        s.m.hb[t]      = d0 * rstd * lng[t]      + lnb[t];
        s.m.hb[t + 32] = d1 * rstd * lng[t + 32] + lnb[t + 32];
    }
    __syncthreads();

    // output layer: 64 -> 128 + residual; 2-way K-split
    {
        const int col = t & 127;
        const int hf  = t >> 7;
        float acc = 0.f;
        const int k0 = hf * 32;
#pragma unroll 8
        for (int k = k0; k < k0 + 32; ++k)
            acc = fmaf(s.m.hb[k], __ldg(&W3[k * HDIM + col]), acc);
        s.m.part3[hf][col] = acc;
    }
    __syncthreads();
    if (t < HDIM) {
        int o = b * HDIM + t;
        out[o] = u[o] + b3[t] + s.m.part3[0][t] + s.m.part3[1][t];
    }
}

// ---------------- launch ----------------
extern "C" void kernel_launch(void* const* d_in, const int* in_sizes, int n_in,
                              void* d_out, int out_size) {
    const float* x     = (const float*)d_in[0];
    // d_in[1] edge_index, d_in[2] edge_attr : unused by the forward
    const float* u     = (const float*)d_in[3];
    const int*   batch = (const int*)d_in[4];
    const float* W0    = (const float*)d_in[5];
    const float* b0    = (const float*)d_in[6];
    const float* W1    = (const float*)d_in[7];
    const float* b1    = (const float*)d_in[8];
    const float* W2    = (const float*)d_in[9];
    const float* b2    = (const float*)d_in[10];
    const float* lng   = (const float*)d_in[11];
    const float* lnb   = (const float*)d_in[12];
    const float* W3    = (const float*)d_in[13];
    const float* b3    = (const float*)d_in[14];
    float* out = (float*)d_out;

    const int N = in_sizes[0] / HDIM;
    const int B = in_sizes[3] / HDIM;

    fused_one<<<B, 256>>>(x, batch, N, u, W0, b0, W1, b1, W2, b2,
                          lng, lnb, W3, b3, out);
}

// round 17
// speedup vs baseline: 1.5183x; 1.5183x over previous
#include <cuda_runtime.h>
#include <cuda_bf16.h>
#include <cstdint>

#define HDIM 128
#define MH 64
#define MAXB 2048
#define LN_EPS 1e-5f

// ===== one graph : two blocks =====
// batch is sorted; graph b's rows are [lb(b), lb(b+1)). Block pair (2b, 2b+1)
// splits the range in half. Each block streams its half with the R14-proven
// float2 8-deep layout, publishes per-column stats to plain scratch
// (fully overwritten each replay), then takes a ticket: the SECOND arriver
// combines both halves and runs the MLP; the first simply exits (its SM slot
// is backfilled by the HW scheduler -> straggle smoothing).
__device__ float g_half[2 * MAXB][4][HDIM];   // [blk][sum,sq,min,max][col]
__device__ int   g_flag[MAXB];                // pair tickets (combiner resets)

struct MlpBufs {
    float part0[16][MH + 1];
    float part1[4][MH + 1];
    float part3[2][HDIM];
    float h0[MH];
    float hb[MH];
};
union TailU {
    float red[4][4][HDIM];     // 8 KB: per-group stats publish
    MlpBufs m;                 // ~7.2 KB
};

__global__ void __launch_bounds__(256, 7) fused_split(
    const float* __restrict__ x, const int* __restrict__ batch, int N,
    const float* __restrict__ u,
    const float* __restrict__ W0, const float* __restrict__ b0,
    const float* __restrict__ W1, const float* __restrict__ b1,
    const float* __restrict__ W2, const float* __restrict__ b2,
    const float* __restrict__ lng, const float* __restrict__ lnb,
    const float* __restrict__ W3, const float* __restrict__ b3,
    float* __restrict__ out) {
    const int blk = blockIdx.x;
    const int b = blk >> 1;          // graph id
    const int h = blk & 1;           // half id
    const int t = threadIdx.x;

    __shared__ int bounds[2];
    __shared__ int ticket;
    __shared__ TailU s;
    __shared__ float concat[5 * HDIM];

    // ---- bounds: threads 0,1 binary-search lower_bound(b), lower_bound(b+1)
    if (t < 2) {
        int target = b + t;
        int lo = 0, hi = N;
        while (lo < hi) {
            int mid = (lo + hi) >> 1;
            if (__ldg(&batch[mid]) < target) lo = mid + 1;
            else hi = mid;
        }
        bounds[t] = lo;
    }
    __syncthreads();
    const int slo = bounds[0], shi = bounds[1];
    const int cnt = shi - slo;                     // full segment count
    const int mid = slo + ((cnt + 1) >> 1);
    const int lo = h ? mid : slo;
    const int hi = h ? shi : mid;

    // ---- stream my half: 4 groups x 64 threads; thread covers cols
    //      [2*cp, 2*cp+1] via float2; rows lo+grp, stride 4 (R14-proven).
    const int cp  = t & 63;
    const int grp = t >> 6;
    float sx = 0.f, sy = 0.f, qx = 0.f, qy = 0.f;
    float mnx = __int_as_float(0x7F800000), mny = mnx;   // +inf
    float mxx = __int_as_float(0xFF800000), mxy = mxx;   // -inf

    int r = lo + grp;
    const float2* xp = (const float2*)x + (long long)r * (HDIM / 2) + cp;
    for (; r + 28 < hi; r += 32) {   // 8 rows per group per iter (stride 4)
        float2 v[8];
#pragma unroll
        for (int j = 0; j < 8; ++j) v[j] = __ldcs(xp + j * 4 * (HDIM / 2));
#pragma unroll
        for (int j = 0; j < 8; ++j) {
            float ax = v[j].x, ay = v[j].y;
            sx += ax; sy += ay;
            qx = fmaf(ax, ax, qx); qy = fmaf(ay, ay, qy);
            mnx = fminf(mnx, ax); mny = fminf(mny, ay);
            mxx = fmaxf(mxx, ax); mxy = fmaxf(mxy, ay);
        }
        xp += 32 * (HDIM / 2);
    }
    for (; r < hi; r += 4) {
        float2 v = __ldcs(xp);
        sx += v.x; sy += v.y;
        qx = fmaf(v.x, v.x, qx); qy = fmaf(v.y, v.y, qy);
        mnx = fminf(mnx, v.x); mny = fminf(mny, v.y);
        mxx = fmaxf(mxx, v.x); mxy = fmaxf(mxy, v.y);
        xp += 4 * (HDIM / 2);
    }

    // ---- all 4 groups publish; 128 threads reduce + write scratch ----
    s.red[grp][0][2 * cp] = sx;  s.red[grp][0][2 * cp + 1] = sy;
    s.red[grp][1][2 * cp] = qx;  s.red[grp][1][2 * cp + 1] = qy;
    s.red[grp][2][2 * cp] = mnx; s.red[grp][2][2 * cp + 1] = mny;
    s.red[grp][3][2 * cp] = mxx; s.red[grp][3][2 * cp + 1] = mxy;
    __syncthreads();
    if (t < HDIM) {
        float ss = s.red[0][0][t] + s.red[1][0][t] + s.red[2][0][t] + s.red[3][0][t];
        float qq = s.red[0][1][t] + s.red[1][1][t] + s.red[2][1][t] + s.red[3][1][t];
        float nn = fminf(fminf(s.red[0][2][t], s.red[1][2][t]),
                         fminf(s.red[2][2][t], s.red[3][2][t]));
        float mm = fmaxf(fmaxf(s.red[0][3][t], s.red[1][3][t]),
                         fmaxf(s.red[2][3][t], s.red[3][3][t]));
        g_half[blk][0][t] = ss;
        g_half[blk][1][t] = qq;
        g_half[blk][2][t] = nn;
        g_half[blk][3][t] = mm;
    }
    __syncthreads();

    // ---- ticket: first arriver exits, second combines ----
    __threadfence();
    if (t == 0) ticket = atomicAdd(&g_flag[b], 1);
    __syncthreads();
    if (ticket == 0) return;
    if (t == 0) g_flag[b] = 0;       // reset for next replay
    __threadfence();                  // acquire peer's scratch writes

    // ---- combine halves, build concat ----
    const int peer = blk ^ 1;
    if (t < HDIM) {
        float ss = g_half[blk][0][t] + __ldg(&g_half[peer][0][t]);
        float qq = g_half[blk][1][t] + __ldg(&g_half[peer][1][t]);
        float nn = fminf(g_half[blk][2][t], __ldg(&g_half[peer][2][t]));
        float mm = fmaxf(g_half[blk][3][t], __ldg(&g_half[peer][3][t]));
        float cv = fmaxf((float)cnt, 1.0f);
        float me = ss / cv;
        concat[t]            = u[b * HDIM + t];
        concat[HDIM + t]     = ss;
        concat[2 * HDIM + t] = nn;
        concat[3 * HDIM + t] = mm;
        concat[4 * HDIM + t] = qq / cv - me * me;
    }
    __syncthreads();

    // ================= MLP (R7-proven structure, single graph) =============
    {
        const int mg = (t & 15) * 4;
        const int q  = t >> 4;
        float a0 = 0.f, a1 = 0.f, a2 = 0.f, a3 = 0.f;
        const int k0 = q * 40;
#pragma unroll 8
        for (int k = k0; k < k0 + 40; ++k) {
            float c = concat[k];
            float4 w = *(const float4*)&W0[k * MH + mg];
            a0 = fmaf(c, w.x, a0);
            a1 = fmaf(c, w.y, a1);
            a2 = fmaf(c, w.z, a2);
            a3 = fmaf(c, w.w, a3);
        }
        s.m.part0[q][mg + 0] = a0;
        s.m.part0[q][mg + 1] = a1;
        s.m.part0[q][mg + 2] = a2;
        s.m.part0[q][mg + 3] = a3;
    }
    __syncthreads();
    if (t < MH) {
        float sum = 0.f;
#pragma unroll
        for (int q = 0; q < 16; ++q) sum += s.m.part0[q][t];
        s.m.h0[t] = fmaxf(sum + b0[t], 0.f);
    }
    __syncthreads();

    {
        const int m = t & 63;
        const int q = t >> 6;
        float acc = 0.f;
        const int k0 = q * 16;
#pragma unroll
        for (int k = k0; k < k0 + 16; ++k)
            acc = fmaf(s.m.h0[k], __ldg(&W1[k * MH + m]), acc);
        s.m.part1[q][m] = acc;
    }
    __syncthreads();
    if (t < MH)
        s.m.hb[t] = fmaxf(s.m.part1[0][t] + s.m.part1[1][t] + s.m.part1[2][t] +
                          s.m.part1[3][t] + b1[t], 0.f);
    __syncthreads();

    {
        const int m = t & 63;
        const int q = t >> 6;
        float acc = 0.f;
        const int k0 = q * 16;
#pragma unroll
        for (int k = k0; k < k0 + 16; ++k)
            acc = fmaf(s.m.hb[k], __ldg(&W2[k * MH + m]), acc);
        s.m.part1[q][m] = acc;
    }
    __syncthreads();
    if (t < MH)
        s.m.h0[t] = fmaxf(s.m.part1[0][t] + s.m.part1[1][t] + s.m.part1[2][t] +
                          s.m.part1[3][t] + b2[t], 0.f);
    __syncthreads();

    if (t < 32) {
        float v0 = s.m.h0[t], v1 = s.m.h0[t + 32];
        float sum = v0 + v1;
#pragma unroll
        for (int o = 16; o > 0; o >>= 1) sum += __shfl_xor_sync(0xFFFFFFFF, sum, o);
        float mu = sum * (1.0f / MH);
        float d0 = v0 - mu, d1 = v1 - mu;
        float vs = d0 * d0 + d1 * d1;
#pragma unroll
        for (int o = 16; o > 0; o >>= 1) vs += __shfl_xor_sync(0xFFFFFFFF, vs, o);
        float rstd = rsqrtf(vs * (1.0f / MH) + LN_EPS);
        s.m.hb[t]      = d0 * rstd * lng[t]      + lnb[t];
        s.m.hb[t + 32] = d1 * rstd * lng[t + 32] + lnb[t + 32];
    }
    __syncthreads();

    {
        const int col = t & 127;
        const int hf  = t >> 7;
        float acc = 0.f;
        const int k0 = hf * 32;
#pragma unroll 8
        for (int k = k0; k < k0 + 32; ++k)
            acc = fmaf(s.m.hb[k], __ldg(&W3[k * HDIM + col]), acc);
        s.m.part3[hf][col] = acc;
    }
    __syncthreads();
    if (t < HDIM) {
        int o = b * HDIM + t;
        out[o] = u[o] + b3[t] + s.m.part3[0][t] + s.m.part3[1][t];
    }
}

// ---------------- launch ----------------
extern "C" void kernel_launch(void* const* d_in, const int* in_sizes, int n_in,
                              void* d_out, int out_size) {
    const float* x     = (const float*)d_in[0];
    // d_in[1] edge_index, d_in[2] edge_attr : unused by the forward
    const float* u     = (const float*)d_in[3];
    const int*   batch = (const int*)d_in[4];
    const float* W0    = (const float*)d_in[5];
    const float* b0    = (const float*)d_in[6];
    const float* W1    = (const float*)d_in[7];
    const float* b1    = (const float*)d_in[8];
    const float* W2    = (const float*)d_in[9];
    const float* b2    = (const float*)d_in[10];
    const float* lng   = (const float*)d_in[11];
    const float* lnb   = (const float*)d_in[12];
    const float* W3    = (const float*)d_in[13];
    const float* b3    = (const float*)d_in[14];
    float* out = (float*)d_out;

    const int N = in_sizes[0] / HDIM;
    int B = in_sizes[3] / HDIM;
    if (B > MAXB) B = MAXB;

    fused_split<<<2 * B, 256>>>(x, batch, N, u, W0, b0, W1, b1, W2, b2,
                                lng, lnb, W3, b3, out);
}